// round 7
// baseline (speedup 1.0000x reference)
#include <cuda_runtime.h>
#include <cstdint>

#define NN 13
#define HD 128
#define NLAYER 8
#define NJ 17
#define DMAX 33
#define OBSD 348
#define SPC 8                  // samples per CTA
#define MREAL 104              // SPC*NN rows
#define XDST 392               // xs row stride: [0,256) dup x, [264,392) agg/h
#define AGG_OFF 264
#define NTHREADS 512
#define KTOT 256
#define KC 64
#define XS_FLOATS (MREAL*XDST) // 40768
#define WB_FLOATS (2*KC*HD)    // 16384

__constant__ int c_feat[NN][DMAX] = {
  {0,1,2,3,4,22,23,24,25,26,27,45,46,47,48,49,50,51,52,53,54,175,176,177,178,179,180,270,271,272,273,274,275},
  {5,6,28,29,55,56,57,58,59,60,61,62,63,64,181,182,183,184,185,186,276,277,278,279,280,281,0,0,0,0,0,0,0},
  {7,30,65,66,67,68,69,70,71,72,73,74,187,188,189,190,191,192,253,254,255,282,283,284,285,286,287,0,0,0,0,0,0},
  {8,9,10,11,31,32,33,34,75,76,77,78,79,80,81,82,83,84,193,194,195,196,197,198,256,257,258,288,289,290,291,292,293},
  {11,34,85,86,87,88,89,90,91,92,93,94,199,200,201,202,203,204,259,294,295,296,297,298,299,0,0,0,0,0,0,0,0},
  {95,96,97,98,99,100,101,102,103,104,205,206,207,208,209,210,300,301,302,303,304,305,0,0,0,0,0,0,0,0,0,0,0},
  {12,13,14,15,35,36,37,38,105,106,107,108,109,110,111,112,113,114,211,212,213,214,215,216,260,261,262,306,307,308,309,310,311},
  {15,38,115,116,117,118,119,120,121,122,123,124,217,218,219,220,221,222,263,312,313,314,315,316,317,0,0,0,0,0,0,0,0},
  {125,126,127,128,129,130,131,132,133,134,223,224,225,226,227,228,318,319,320,321,322,323,0,0,0,0,0,0,0,0,0,0,0},
  {16,17,18,39,40,41,135,136,137,138,139,140,141,142,143,144,229,230,231,232,233,234,264,265,324,325,326,327,328,329,0,0,0},
  {18,41,145,146,147,148,149,150,151,152,153,154,235,236,237,238,239,240,266,330,331,332,333,334,335,0,0,0,0,0,0,0,0},
  {19,20,21,42,43,44,155,156,157,158,159,160,161,162,163,164,241,242,243,244,245,246,267,268,336,337,338,339,340,341,0,0,0},
  {21,44,165,166,167,168,169,170,171,172,173,174,247,248,249,250,251,252,269,342,343,344,345,346,347,0,0,0,0,0,0,0,0}
};
__constant__ int c_dcnt[NN] = {33,26,27,33,25,22,33,25,22,30,25,30,25};

__constant__ int c_nbr[NN][3] = {
  {1,9,11},{0,2,0},{1,3,6},{2,4,0},{3,5,0},{4,0,0},{2,7,0},
  {6,8,0},{7,0,0},{0,10,0},{9,0,0},{0,12,0},{11,0,0}
};
__constant__ int c_deg[NN] = {3,2,3,2,2,1,2,2,1,2,1,2,1};

__constant__ int c_jm0[NJ] = {1,1,1,2,2,2,3,2,2,2,6,0,0,9,0,0,11};
__constant__ int c_jm1[NJ] = {2,2,2,3,3,3,4,6,6,6,7,9,9,10,11,11,12};

__device__ __forceinline__ float eluf(float x) {
    return x > 0.0f ? x : expm1f(x);
}
__device__ __forceinline__ unsigned long long pk2(float lo, float hi) {
    unsigned long long r;
    asm("mov.b64 %0, {%1, %2};" : "=l"(r) : "f"(lo), "f"(hi));
    return r;
}
__device__ __forceinline__ void upk2(unsigned long long v, float& lo, float& hi) {
    asm("mov.b64 {%0, %1}, %2;" : "=f"(lo), "=f"(hi) : "l"(v));
}
// Blackwell packed dual-FP32 FMA: 2 exact fp32 FMAs per issue slot
__device__ __forceinline__ void fma2(unsigned long long& d, unsigned long long a, unsigned long long b) {
    asm("fma.rn.f32x2 %0, %1, %2, %0;" : "+l"(d) : "l"(a), "l"(b));
}

__global__ __launch_bounds__(NTHREADS, 1)
void gnn_kernel(const float* __restrict__ obs,
                const float* __restrict__ W1, const float* __restrict__ b1,
                const float* __restrict__ W2, const float* __restrict__ b2,
                const float* __restrict__ Wmsg, const float* __restrict__ bmsg,
                const float* __restrict__ Wout, const float* __restrict__ bout,
                float* __restrict__ out)
{
    extern __shared__ float sm[];
    float* xs = sm;                    // [104][392]
    float* wb = sm + XS_FLOATS;        // 2 x [64][128] weight ping-pong; head aliases obs buffer

    const int tid = threadIdx.x;
    const int base_s = blockIdx.x * SPC;
    const int tx = tid & 31;           // cols 4tx..4tx+3
    const int ty = tid >> 5;           // warp / row group

    // ======== load obs tile (aliases wb; dead before first weight store) ========
    float* obsb = wb;                  // [SPC][OBSD] = 2784 floats
    {
        const float4* g = (const float4*)(obs + (size_t)base_s * OBSD);
        float4* o4 = (float4*)obsb;
        for (int i = tid; i < SPC * OBSD / 4; i += NTHREADS) o4[i] = g[i];
    }
    __syncthreads();

    // ======== encoder phase 1: h = elu(gather(obs) @ W1[n] + b1[n]) -> xs agg cols ========
    if (ty < NN) {
        const int n = ty;
        unsigned long long acc[SPC][2];
        {
            ulonglong2 bv = *(const ulonglong2*)(b1 + n * HD + 4 * tx);
            #pragma unroll
            for (int s = 0; s < SPC; ++s) { acc[s][0] = bv.x; acc[s][1] = bv.y; }
        }
        const int dc = c_dcnt[n];
        #pragma unroll 1
        for (int d = 0; d < dc; ++d) {
            const int fi = c_feat[n][d];
            ulonglong2 w = *(const ulonglong2*)(W1 + (n * DMAX + d) * HD + 4 * tx);
            #pragma unroll
            for (int s = 0; s < SPC; ++s) {
                float xe = obsb[s * OBSD + fi];
                unsigned long long p = pk2(xe, xe);
                fma2(acc[s][0], p, w.x); fma2(acc[s][1], p, w.y);
            }
        }
        #pragma unroll
        for (int s = 0; s < SPC; ++s) {
            float* dst = xs + (s * NN + n) * XDST + AGG_OFF + 4 * tx;
            float l0, h0, l1, h1;
            upk2(acc[s][0], l0, h0);
            upk2(acc[s][1], l1, h1);
            *(float4*)dst = make_float4(eluf(l0), eluf(h0), eluf(l1), eluf(h1));
        }
    }
    __syncthreads();

    // ======== encoder phase 2: x0 = h @ W2[n] + b2[n] -> xs dup x cols ========
    if (ty < NN) {
        const int n = ty;
        unsigned long long acc[SPC][2];
        {
            ulonglong2 bv = *(const ulonglong2*)(b2 + n * HD + 4 * tx);
            #pragma unroll
            for (int s = 0; s < SPC; ++s) { acc[s][0] = bv.x; acc[s][1] = bv.y; }
        }
        #pragma unroll 2
        for (int k = 0; k < HD; ++k) {
            ulonglong2 w = *(const ulonglong2*)(W2 + (n * HD + k) * HD + 4 * tx);
            #pragma unroll
            for (int s = 0; s < SPC; ++s) {
                float xe = xs[(s * NN + n) * XDST + AGG_OFF + k];
                unsigned long long p = pk2(xe, xe);
                fma2(acc[s][0], p, w.x); fma2(acc[s][1], p, w.y);
            }
        }
        #pragma unroll
        for (int s = 0; s < SPC; ++s) {
            float* dst = xs + (s * NN + n) * XDST + 8 * tx;
            float lo, hi;
            upk2(acc[s][0], lo, hi);
            *(float4*)(dst)     = make_float4(lo, lo, hi, hi);
            upk2(acc[s][1], lo, hi);
            *(float4*)(dst + 4) = make_float4(lo, lo, hi, hi);
        }
    }
    // no sync: layer-0 top sync orders these writes

    // SMSP-balanced row tiling: ty<8 -> 7 rows, ty>=8 -> 6 rows (total 104)
    const int R = (ty < 8) ? 7 : 6;
    const int row0 = (ty < 8) ? ty * 7 : 56 + (ty - 8) * 6;
    int xoff[7];
    #pragma unroll
    for (int r = 0; r < 7; ++r) xoff[r] = (row0 + ((r < R) ? r : R - 1)) * XDST;

    // ======== 8 message-passing layers: out = elu([x|agg] @ Wmsg[l] + bmsg[l]) ========
    for (int l = 0; l < NLAYER; ++l) {
        const float* Wl = Wmsg + (size_t)l * KTOT * HD;

        // prefetch weight chunk 0 into registers (LDG overlaps agg pass)
        float4 wreg[4];
        {
            const float4* g = (const float4*)Wl;
            #pragma unroll
            for (int r = 0; r < 4; ++r) wreg[r] = g[tid + r * NTHREADS];
        }

        __syncthreads();   // encoder / previous writeback complete
        // aggregation from dup x -> non-dup agg cols
        for (int i = tid; i < MREAL * 32; i += NTHREADS) {
            int c0 = (i & 31) * 4;          // agg cols c0..c0+3
            int m  = i >> 5;
            int n = m % NN;
            int s13 = m - n;
            const float* b0 = xs + (s13 + c_nbr[n][0]) * XDST + 2 * c0;
            float4 f1 = *(const float4*)(b0);
            float4 f2 = *(const float4*)(b0 + 4);
            float4 sum = make_float4(f1.x, f1.z, f2.x, f2.z);
            int dg = c_deg[n];
            #pragma unroll
            for (int e = 1; e < 3; ++e)
                if (e < dg) {
                    const float* be = xs + (s13 + c_nbr[n][e]) * XDST + 2 * c0;
                    float4 g1 = *(const float4*)(be);
                    float4 g2 = *(const float4*)(be + 4);
                    sum.x += g1.x; sum.y += g1.z; sum.z += g2.x; sum.w += g2.z;
                }
            *(float4*)(xs + m * XDST + AGG_OFF + c0) = sum;
        }
        // store chunk 0 to ping buffer
        {
            float4* d4 = (float4*)wb;
            #pragma unroll
            for (int r = 0; r < 4; ++r) d4[tid + r * NTHREADS] = wreg[r];
        }

        unsigned long long acc[7][2];
        {
            ulonglong2 bv = *(const ulonglong2*)(bmsg + l * HD + 4 * tx);
            #pragma unroll
            for (int r = 0; r < 7; ++r) { acc[r][0] = bv.x; acc[r][1] = bv.y; }
        }

        for (int kc = 0; kc < KTOT / KC; ++kc) {
            __syncthreads();   // current buffer staged; prior reads of next buffer done
            if (kc < KTOT / KC - 1) {   // prefetch next chunk into registers
                const float4* g = (const float4*)(Wl + (kc + 1) * KC * HD);
                #pragma unroll
                for (int r = 0; r < 4; ++r) wreg[r] = g[tid + r * NTHREADS];
            }
            const float* wt = wb + (kc & 1) * (KC * HD);

            if (kc < 2) {
                // x half: duplicated operands, no pk2
                const float* xk = xs + kc * (2 * KC);   // dup floats base
                #pragma unroll 1
                for (int k2 = 0; k2 < KC; k2 += 2) {
                    ulonglong2 a[7];
                    #pragma unroll
                    for (int r = 0; r < 7; ++r)
                        a[r] = *(const ulonglong2*)(xk + xoff[r] + 2 * k2);
                    #pragma unroll
                    for (int kk = 0; kk < 2; ++kk) {
                        ulonglong2 w = *(const ulonglong2*)(wt + (k2 + kk) * HD + 4 * tx);
                        #pragma unroll
                        for (int r = 0; r < 7; ++r) {
                            unsigned long long p = kk ? a[r].y : a[r].x;
                            fma2(acc[r][0], p, w.x);
                            fma2(acc[r][1], p, w.y);
                        }
                    }
                }
            } else {
                // agg half: scalar operands + pk2
                const float* ak = xs + AGG_OFF + (kc - 2) * KC;
                #pragma unroll 1
                for (int k4 = 0; k4 < KC; k4 += 4) {
                    float4 a[7];
                    #pragma unroll
                    for (int r = 0; r < 7; ++r)
                        a[r] = *(const float4*)(ak + xoff[r] + k4);
                    #pragma unroll
                    for (int kk = 0; kk < 4; ++kk) {
                        ulonglong2 w = *(const ulonglong2*)(wt + (k4 + kk) * HD + 4 * tx);
                        #pragma unroll
                        for (int r = 0; r < 7; ++r) {
                            const float* af = (const float*)&a[r];
                            unsigned long long p = pk2(af[kk], af[kk]);
                            fma2(acc[r][0], p, w.x);
                            fma2(acc[r][1], p, w.y);
                        }
                    }
                }
            }

            if (kc < KTOT / KC - 1) {   // store next chunk to pong buffer
                float4* d4 = (float4*)(wb + ((kc + 1) & 1) * (KC * HD));
                #pragma unroll
                for (int r = 0; r < 4; ++r) d4[tid + r * NTHREADS] = wreg[r];
            }
        }
        __syncthreads();
        // ELU + duplicated writeback
        #pragma unroll
        for (int r = 0; r < 7; ++r) {
            if (r < R) {
                float* dst = xs + (row0 + r) * XDST + 8 * tx;
                float lo, hi;
                upk2(acc[r][0], lo, hi);
                lo = eluf(lo); hi = eluf(hi);
                *(float4*)(dst)     = make_float4(lo, lo, hi, hi);
                upk2(acc[r][1], lo, hi);
                lo = eluf(lo); hi = eluf(hi);
                *(float4*)(dst + 4) = make_float4(lo, lo, hi, hi);
            }
        }
    }
    __syncthreads();

    // ======== joint readout (dup x: x[m][c] at xs[m][2c]) ========
    const int lane = tid & 31;
    const int wrp = tid >> 5;
    for (int t = wrp; t < SPC * NJ; t += NTHREADS / 32) {
        int s = t / NJ, j = t - s * NJ;
        const float* r0 = xs + (s * NN + c_jm0[j]) * XDST + 8 * lane;
        const float* r1 = xs + (s * NN + c_jm1[j]) * XDST + 8 * lane;
        const float* wj = Wout + j * 2 * HD + 4 * lane;
        float4 xa = *(const float4*)(r0);
        float4 xb = *(const float4*)(r0 + 4);
        float4 ya = *(const float4*)(r1);
        float4 yb = *(const float4*)(r1 + 4);
        float4 w0 = *(const float4*)(wj);
        float4 w1 = *(const float4*)(wj + HD);
        float sum = xa.x * w0.x + xa.z * w0.y + xb.x * w0.z + xb.z * w0.w
                  + ya.x * w1.x + ya.z * w1.y + yb.x * w1.z + yb.z * w1.w;
        #pragma unroll
        for (int o = 16; o; o >>= 1)
            sum += __shfl_xor_sync(0xffffffffu, sum, o);
        if (lane == 0)
            out[(size_t)(base_s + s) * NJ + j] = sum + bout[j];
    }
}

extern "C" void kernel_launch(void* const* d_in, const int* in_sizes, int n_in,
                              void* d_out, int out_size) {
    const float* obs  = (const float*)d_in[0];
    const float* W1   = (const float*)d_in[1];
    const float* b1   = (const float*)d_in[2];
    const float* W2   = (const float*)d_in[3];
    const float* b2   = (const float*)d_in[4];
    const float* Wmsg = (const float*)d_in[5];
    const float* bmsg = (const float*)d_in[6];
    const float* Wout = (const float*)d_in[7];
    const float* bout = (const float*)d_in[8];
    float* out = (float*)d_out;

    int B = in_sizes[0] / OBSD;
    int nblk = B / SPC;
    size_t smem = (size_t)(XS_FLOATS + WB_FLOATS) * sizeof(float); // 228,608 B

    cudaFuncSetAttribute(gnn_kernel, cudaFuncAttributeMaxDynamicSharedMemorySize, (int)smem);
    gnn_kernel<<<nblk, NTHREADS, smem>>>(obs, W1, b1, W2, b2, Wmsg, bmsg, Wout, bout, out);
}

// round 9
// speedup vs baseline: 1.1821x; 1.1821x over previous
#include <cuda_runtime.h>
#include <cstdint>

#define NN 13
#define HD 128
#define NLAYER 8
#define NJ 17
#define DMAX 33
#define OBSD 348
#define SPC 4                 // samples per CTA
#define MREAL (SPC*NN)        // 52 rows
#define XST 260               // xs row stride (floats), 16B-aligned rows
#define NTHREADS 256
#define KTOT 256
#define KC 32
#define NCHUNK (KTOT/KC)      // 8

__constant__ int c_feat[NN][DMAX] = {
  {0,1,2,3,4,22,23,24,25,26,27,45,46,47,48,49,50,51,52,53,54,175,176,177,178,179,180,270,271,272,273,274,275},
  {5,6,28,29,55,56,57,58,59,60,61,62,63,64,181,182,183,184,185,186,276,277,278,279,280,281,0,0,0,0,0,0,0},
  {7,30,65,66,67,68,69,70,71,72,73,74,187,188,189,190,191,192,253,254,255,282,283,284,285,286,287,0,0,0,0,0,0},
  {8,9,10,11,31,32,33,34,75,76,77,78,79,80,81,82,83,84,193,194,195,196,197,198,256,257,258,288,289,290,291,292,293},
  {11,34,85,86,87,88,89,90,91,92,93,94,199,200,201,202,203,204,259,294,295,296,297,298,299,0,0,0,0,0,0,0,0},
  {95,96,97,98,99,100,101,102,103,104,205,206,207,208,209,210,300,301,302,303,304,305,0,0,0,0,0,0,0,0,0,0,0},
  {12,13,14,15,35,36,37,38,105,106,107,108,109,110,111,112,113,114,211,212,213,214,215,216,260,261,262,306,307,308,309,310,311},
  {15,38,115,116,117,118,119,120,121,122,123,124,217,218,219,220,221,222,263,312,313,314,315,316,317,0,0,0,0,0,0,0,0},
  {125,126,127,128,129,130,131,132,133,134,223,224,225,226,227,228,318,319,320,321,322,323,0,0,0,0,0,0,0,0,0,0,0},
  {16,17,18,39,40,41,135,136,137,138,139,140,141,142,143,144,229,230,231,232,233,234,264,265,324,325,326,327,328,329,0,0,0},
  {18,41,145,146,147,148,149,150,151,152,153,154,235,236,237,238,239,240,266,330,331,332,333,334,335,0,0,0,0,0,0,0,0},
  {19,20,21,42,43,44,155,156,157,158,159,160,161,162,163,164,241,242,243,244,245,246,267,268,336,337,338,339,340,341,0,0,0},
  {21,44,165,166,167,168,169,170,171,172,173,174,247,248,249,250,251,252,269,342,343,344,345,346,347,0,0,0,0,0,0,0,0}
};
__constant__ int c_dcnt[NN] = {33,26,27,33,25,22,33,25,22,30,25,30,25};

__constant__ int c_nbr[NN][3] = {
  {1,9,11},{0,2,0},{1,3,6},{2,4,0},{3,5,0},{4,0,0},{2,7,0},
  {6,8,0},{7,0,0},{0,10,0},{9,0,0},{0,12,0},{11,0,0}
};
__constant__ int c_deg[NN] = {3,2,3,2,2,1,2,2,1,2,1,2,1};

__constant__ int c_jm0[NJ] = {1,1,1,2,2,2,3,2,2,2,6,0,0,9,0,0,11};
__constant__ int c_jm1[NJ] = {2,2,2,3,3,3,4,6,6,6,7,9,9,10,11,11,12};

__device__ __forceinline__ float eluf(float x) {
    return x > 0.0f ? x : expm1f(x);
}
__device__ __forceinline__ unsigned long long pk2(float lo, float hi) {
    unsigned long long r;
    asm("mov.b64 %0, {%1, %2};" : "=l"(r) : "f"(lo), "f"(hi));
    return r;
}
__device__ __forceinline__ void upk2(unsigned long long v, float& lo, float& hi) {
    asm("mov.b64 {%0, %1}, %2;" : "=f"(lo), "=f"(hi) : "l"(v));
}
// Blackwell packed dual-FP32 FMA (exact IEEE fp32 lanes)
__device__ __forceinline__ void fma2(unsigned long long& d, unsigned long long a, unsigned long long b) {
    asm("fma.rn.f32x2 %0, %1, %2, %0;" : "+l"(d) : "l"(a), "l"(b));
}

__global__ __launch_bounds__(NTHREADS, 2)
void gnn_kernel(const float* __restrict__ obs,
                const float* __restrict__ W1, const float* __restrict__ b1,
                const float* __restrict__ W2, const float* __restrict__ b2,
                const float* __restrict__ Wmsg, const float* __restrict__ bmsg,
                const float* __restrict__ Wout, const float* __restrict__ bout,
                float* __restrict__ out)
{
    extern __shared__ float sm[];
    float* xs = sm;                        // [52][260]: cols 0..127 = x, 128..255 = agg/h
    float* wb = sm + MREAL * XST;          // 2 x [32][128] weight ping-pong; head aliases obs buffer

    const int tid = threadIdx.x;
    const int base_s = blockIdx.x * SPC;

    const int tx = tid & 31;               // ull column pair: cols {tx, tx+32} (of 64)
    const int ty = tid >> 5;               // 0..7 row group / warp

    // ======== load obs tile (aliases wb buffer 0; dead before first weight store) ========
    float* obsb = wb;                      // [SPC][OBSD] = 1392 floats
    {
        const float4* g = (const float4*)(obs + (size_t)base_s * OBSD);
        float4* o4 = (float4*)obsb;
        for (int i = tid; i < SPC * OBSD / 4; i += NTHREADS) o4[i] = g[i];
    }
    __syncthreads();

    // ======== encoder phase 1: h = elu(gather(obs) @ W1[n] + b1[n]) -> xs agg cols ========
    for (int n = ty; n < NN; n += 8) {
        unsigned long long acc[SPC][2];
        {
            const unsigned long long* bp = (const unsigned long long*)(b1 + n * HD);
            unsigned long long b0 = bp[tx], b1v = bp[tx + 32];
            #pragma unroll
            for (int s = 0; s < SPC; ++s) { acc[s][0] = b0; acc[s][1] = b1v; }
        }
        const int dc = c_dcnt[n];
        #pragma unroll 1
        for (int d = 0; d < dc; ++d) {
            const int fi = c_feat[n][d];
            const unsigned long long* wr =
                (const unsigned long long*)(W1 + (n * DMAX + d) * HD);
            unsigned long long w0 = wr[tx], w1 = wr[tx + 32];
            #pragma unroll
            for (int s = 0; s < SPC; ++s) {
                float xe = obsb[s * OBSD + fi];
                unsigned long long p = pk2(xe, xe);
                fma2(acc[s][0], p, w0); fma2(acc[s][1], p, w1);
            }
        }
        #pragma unroll
        for (int s = 0; s < SPC; ++s) {
            float* dst = xs + (s * NN + n) * XST + HD;
            float lo, hi;
            upk2(acc[s][0], lo, hi);
            *(float2*)(dst + 2 * tx) = make_float2(eluf(lo), eluf(hi));
            upk2(acc[s][1], lo, hi);
            *(float2*)(dst + 2 * tx + 64) = make_float2(eluf(lo), eluf(hi));
        }
    }
    __syncthreads();

    // ======== encoder phase 2: x0 = h @ W2[n] + b2[n] -> xs x cols ========
    for (int n = ty; n < NN; n += 8) {
        unsigned long long acc[SPC][2];
        {
            const unsigned long long* bp = (const unsigned long long*)(b2 + n * HD);
            unsigned long long b0 = bp[tx], b1v = bp[tx + 32];
            #pragma unroll
            for (int s = 0; s < SPC; ++s) { acc[s][0] = b0; acc[s][1] = b1v; }
        }
        #pragma unroll 2
        for (int k = 0; k < HD; ++k) {
            const unsigned long long* wr =
                (const unsigned long long*)(W2 + (n * HD + k) * HD);
            unsigned long long w0 = wr[tx], w1 = wr[tx + 32];
            #pragma unroll
            for (int s = 0; s < SPC; ++s) {
                float xe = xs[(s * NN + n) * XST + HD + k];
                unsigned long long p = pk2(xe, xe);
                fma2(acc[s][0], p, w0); fma2(acc[s][1], p, w1);
            }
        }
        #pragma unroll
        for (int s = 0; s < SPC; ++s) {
            float* dst = xs + (s * NN + n) * XST;
            float lo, hi;
            upk2(acc[s][0], lo, hi);
            *(float2*)(dst + 2 * tx) = make_float2(lo, hi);
            upk2(acc[s][1], lo, hi);
            *(float2*)(dst + 2 * tx + 64) = make_float2(lo, hi);
        }
    }

    // SMSP-balanced row tiling: ty<4 -> 7 rows, ty>=4 -> 6 rows (total 52)
    const int R = (ty < 4) ? 7 : 6;
    const int row0 = (ty < 4) ? ty * 7 : 28 + (ty - 4) * 6;
    int xoff[7];
    #pragma unroll
    for (int r = 0; r < 7; ++r) xoff[r] = (row0 + ((r < R) ? r : R - 1)) * XST;

    // ======== 8 message-passing layers ========
    for (int l = 0; l < NLAYER; ++l) {
        const float* Wl = Wmsg + (size_t)l * KTOT * HD;

        // prefetch weight chunk 0 into registers (LDG overlaps agg pass)
        float4 wreg[4];
        {
            const float4* g = (const float4*)Wl;
            #pragma unroll
            for (int r = 0; r < 4; ++r) wreg[r] = g[tid + r * NTHREADS];
        }

        __syncthreads();   // encoder / previous writeback complete
        // aggregation: agg[s,n] = sum_{nb} x[s,nb]  (float4 over h)
        for (int i = tid; i < MREAL * (HD / 4); i += NTHREADS) {
            int h4 = i & 31;
            int m  = i >> 5;
            int n = m % NN;
            int s13 = m - n;
            float4 sum = *(const float4*)(xs + (s13 + c_nbr[n][0]) * XST + h4 * 4);
            int dg = c_deg[n];
            #pragma unroll
            for (int e = 1; e < 3; ++e)
                if (e < dg) {
                    float4 v = *(const float4*)(xs + (s13 + c_nbr[n][e]) * XST + h4 * 4);
                    sum.x += v.x; sum.y += v.y; sum.z += v.z; sum.w += v.w;
                }
            *(float4*)(xs + m * XST + HD + h4 * 4) = sum;
        }
        // store chunk 0 to ping buffer
        {
            float4* d4 = (float4*)wb;
            #pragma unroll
            for (int r = 0; r < 4; ++r) d4[tid + r * NTHREADS] = wreg[r];
        }

        unsigned long long acc[7][2];
        {
            const unsigned long long* bp = (const unsigned long long*)(bmsg + l * HD);
            unsigned long long b0 = bp[tx], b1v = bp[tx + 32];
            #pragma unroll
            for (int r = 0; r < 7; ++r) { acc[r][0] = b0; acc[r][1] = b1v; }
        }

        for (int kc = 0; kc < NCHUNK; ++kc) {
            __syncthreads();   // current buffer staged; prior reads of next buffer done
            if (kc < NCHUNK - 1) {   // prefetch next chunk into registers
                const float4* g = (const float4*)(Wl + (kc + 1) * KC * HD);
                #pragma unroll
                for (int r = 0; r < 4; ++r) wreg[r] = g[tid + r * NTHREADS];
            }
            const float* cur = wb + (kc & 1) * (KC * HD);
            const float* xk = xs + kc * KC;
            #pragma unroll 1
            for (int k4 = 0; k4 < KC; k4 += 4) {
                float4 a[7];
                #pragma unroll
                for (int r = 0; r < 7; ++r)
                    a[r] = *(const float4*)(xk + xoff[r] + k4);
                #pragma unroll
                for (int kk = 0; kk < 4; ++kk) {
                    const unsigned long long* wr =
                        (const unsigned long long*)(cur + kk * HD);
                    unsigned long long w0 = wr[tx], w1 = wr[tx + 32];
                    #pragma unroll
                    for (int r = 0; r < 7; ++r) {
                        const float* af = (const float*)&a[r];
                        float xe = af[kk];
                        unsigned long long p = pk2(xe, xe);
                        fma2(acc[r][0], p, w0);
                        fma2(acc[r][1], p, w1);
                    }
                }
                // advance k within the staged chunk without re-deriving pointers
                cur += 4 * HD;
            }
            if (kc < NCHUNK - 1) {   // store next chunk to pong buffer
                float4* d4 = (float4*)(wb + ((kc + 1) & 1) * (KC * HD));
                #pragma unroll
                for (int r = 0; r < 4; ++r) d4[tid + r * NTHREADS] = wreg[r];
            }
        }
        __syncthreads();
        // ELU + writeback
        #pragma unroll
        for (int r = 0; r < 7; ++r) {
            if (r < R) {
                float* dst = xs + (row0 + r) * XST;
                float lo, hi;
                upk2(acc[r][0], lo, hi);
                *(float2*)(dst + 2 * tx) = make_float2(eluf(lo), eluf(hi));
                upk2(acc[r][1], lo, hi);
                *(float2*)(dst + 2 * tx + 64) = make_float2(eluf(lo), eluf(hi));
            }
        }
    }
    __syncthreads();

    // ======== joint readout ========
    const int lane = tid & 31;
    const int wrp = tid >> 5;
    for (int t = wrp; t < SPC * NJ; t += NTHREADS / 32) {
        int s = t / NJ, j = t - s * NJ;
        const float* r0 = xs + (s * NN + c_jm0[j]) * XST;
        const float* r1 = xs + (s * NN + c_jm1[j]) * XST;
        const float* wj = Wout + j * 2 * HD;
        float4 x0 = *(const float4*)(r0 + lane * 4);
        float4 x1 = *(const float4*)(r1 + lane * 4);
        float4 w0 = *(const float4*)(wj + lane * 4);
        float4 w1 = *(const float4*)(wj + HD + lane * 4);
        float sum = x0.x*w0.x + x0.y*w0.y + x0.z*w0.z + x0.w*w0.w
                  + x1.x*w1.x + x1.y*w1.y + x1.z*w1.z + x1.w*w1.w;
        #pragma unroll
        for (int o = 16; o; o >>= 1)
            sum += __shfl_xor_sync(0xffffffffu, sum, o);
        if (lane == 0)
            out[(size_t)(base_s + s) * NJ + j] = sum + bout[j];
    }
}

extern "C" void kernel_launch(void* const* d_in, const int* in_sizes, int n_in,
                              void* d_out, int out_size) {
    const float* obs  = (const float*)d_in[0];
    const float* W1   = (const float*)d_in[1];
    const float* b1   = (const float*)d_in[2];
    const float* W2   = (const float*)d_in[3];
    const float* b2   = (const float*)d_in[4];
    const float* Wmsg = (const float*)d_in[5];
    const float* bmsg = (const float*)d_in[6];
    const float* Wout = (const float*)d_in[7];
    const float* bout = (const float*)d_in[8];
    float* out = (float*)d_out;

    int B = in_sizes[0] / OBSD;
    int nblk = B / SPC;                         // 4096
    size_t smem = (size_t)(MREAL * XST + 2 * KC * HD) * sizeof(float); // 86,848 B

    cudaFuncSetAttribute(gnn_kernel, cudaFuncAttributeMaxDynamicSharedMemorySize, (int)smem);
    gnn_kernel<<<nblk, NTHREADS, smem>>>(obs, W1, b1, W2, b2, Wmsg, bmsg, Wout, bout, out);
}